// round 12
// baseline (speedup 1.0000x reference)
#include <cuda_runtime.h>
#include <cuda_fp16.h>
#include <math.h>
#include <stdint.h>

#define Nn 50000
#define Ee 800000
#define Hh 4
#define Ff 128
#define NEG 0.2f
#define BN_EPS 1e-5f
#define CAP 64            // bucket capacity; P(deg>64) ~ 5e-19 per node

// ---------------- scratch (device globals) ----------------------------------
__device__ __align__(16) __half g_h16[(size_t)Nn * Ff];  // projected features, fp16
__device__ __align__(16) float g_asrc[Nn * Hh];          // per-node src attention logits
__device__ __align__(16) float g_adst[Nn * Hh];          // per-node dst attention logits
__device__ __align__(16) float g_agg[(size_t)Nn * Ff];   // aggregated (pre-BN) output
__device__ __align__(16) int g_csr[(size_t)Nn * CAP];    // per-dst edge buckets (src ids)
// single zero-init region: [0,Nn) = cur, [Nn,Nn+128) = bns, [Nn+128,Nn+256) = bnq,
// [Nn+256] = barrier counter
__device__ __align__(16) int g_zero[Nn + 2 * Ff + 1];
#define P_CUR  (g_zero)
#define P_BNS  ((float*)(g_zero + Nn))
#define P_BNQ  ((float*)(g_zero + Nn + Ff))
#define P_BAR  ((unsigned int*)(g_zero + Nn + 2 * Ff))

__device__ __forceinline__ uint32_t f2tf(float f) {
    uint32_t u;
    asm("cvt.rna.tf32.f32 %0, %1;" : "=r"(u) : "f"(f));
    return u;
}

__device__ __forceinline__ void mma_tf32(float c[4], uint32_t a0, uint32_t a1,
                                         uint32_t a2, uint32_t a3,
                                         uint32_t b0, uint32_t b1) {
    asm volatile(
        "mma.sync.aligned.m16n8k8.row.col.f32.tf32.tf32.f32 "
        "{%0,%1,%2,%3}, {%4,%5,%6,%7}, {%8,%9}, {%0,%1,%2,%3};"
        : "+f"(c[0]), "+f"(c[1]), "+f"(c[2]), "+f"(c[3])
        : "r"(a0), "r"(a1), "r"(a2), "r"(a3), "r"(b0), "r"(b1));
}

// ---------------- K1: h = x @ W^T (tf32 tensor cores) + fused att logits -----
__global__ void gemm_att_kernel(const float* __restrict__ x,
                                const float* __restrict__ W,
                                const float* __restrict__ att_src,
                                const float* __restrict__ att_dst) {
    __shared__ uint32_t xs[128][36];
    __shared__ uint32_t ws[32][136];
    int tid = threadIdx.x;
    int warp = tid >> 5, lane = tid & 31;
    int qid = lane >> 2;
    int tq  = lane & 3;
    int row0 = blockIdx.x * 128;

    float c[16][4];
#pragma unroll
    for (int i = 0; i < 16; i++)
#pragma unroll
        for (int j = 0; j < 4; j++) c[i][j] = 0.f;

    for (int kb = 0; kb < 128; kb += 32) {
#pragma unroll
        for (int i = 0; i < 4; i++) {
            int lin = i * 256 + tid;
            int r = lin >> 3;
            int c4 = (lin & 7) * 4;
            int gr = row0 + r;
            float4 v = (gr < Nn) ? *(const float4*)&x[(size_t)gr * 128 + kb + c4]
                                 : make_float4(0.f, 0.f, 0.f, 0.f);
            uint32_t* dst = &xs[r][c4];
            dst[0] = f2tf(v.x); dst[1] = f2tf(v.y);
            dst[2] = f2tf(v.z); dst[3] = f2tf(v.w);
        }
#pragma unroll
        for (int i = 0; i < 4; i++) {
            int lin = i * 256 + tid;
            int f  = lin & 127;
            int c4 = (lin >> 7) * 4;
            float4 v = *(const float4*)&W[f * 128 + kb + c4];
            ws[c4 + 0][f] = f2tf(v.x);
            ws[c4 + 1][f] = f2tf(v.y);
            ws[c4 + 2][f] = f2tf(v.z);
            ws[c4 + 3][f] = f2tf(v.w);
        }
        __syncthreads();
#pragma unroll
        for (int ks = 0; ks < 4; ks++) {
            int k0 = ks * 8;
            int r = warp * 16 + qid;
            uint32_t a0 = xs[r][k0 + tq];
            uint32_t a1 = xs[r + 8][k0 + tq];
            uint32_t a2 = xs[r][k0 + tq + 4];
            uint32_t a3 = xs[r + 8][k0 + tq + 4];
#pragma unroll
            for (int nt = 0; nt < 16; nt++) {
                uint32_t b0 = ws[k0 + tq][nt * 8 + qid];
                uint32_t b1 = ws[k0 + tq + 4][nt * 8 + qid];
                mma_tf32(c[nt], a0, a1, a2, a3, b0, b1);
            }
        }
        __syncthreads();
    }

    int r0 = row0 + warp * 16 + qid;
    int r1 = r0 + 8;
    float ps0[4] = {0,0,0,0}, ps1[4] = {0,0,0,0};
    float pd0[4] = {0,0,0,0}, pd1[4] = {0,0,0,0};
#pragma unroll
    for (int nt = 0; nt < 16; nt++) {
        int col = nt * 8 + 2 * tq;
        int head = nt >> 2;
        if (r0 < Nn)
            *(__half2*)&g_h16[(size_t)r0 * 128 + col] = __floats2half2_rn(c[nt][0], c[nt][1]);
        if (r1 < Nn)
            *(__half2*)&g_h16[(size_t)r1 * 128 + col] = __floats2half2_rn(c[nt][2], c[nt][3]);
        float as0 = att_src[col], as1 = att_src[col + 1];
        float ad0 = att_dst[col], ad1 = att_dst[col + 1];
        ps0[head] += c[nt][0] * as0 + c[nt][1] * as1;
        ps1[head] += c[nt][2] * as0 + c[nt][3] * as1;
        pd0[head] += c[nt][0] * ad0 + c[nt][1] * ad1;
        pd1[head] += c[nt][2] * ad0 + c[nt][3] * ad1;
    }
#pragma unroll
    for (int hd = 0; hd < 4; hd++) {
        ps0[hd] += __shfl_down_sync(0xFFFFFFFFu, ps0[hd], 1);
        ps0[hd] += __shfl_down_sync(0xFFFFFFFFu, ps0[hd], 2);
        ps1[hd] += __shfl_down_sync(0xFFFFFFFFu, ps1[hd], 1);
        ps1[hd] += __shfl_down_sync(0xFFFFFFFFu, ps1[hd], 2);
        pd0[hd] += __shfl_down_sync(0xFFFFFFFFu, pd0[hd], 1);
        pd0[hd] += __shfl_down_sync(0xFFFFFFFFu, pd0[hd], 2);
        pd1[hd] += __shfl_down_sync(0xFFFFFFFFu, pd1[hd], 1);
        pd1[hd] += __shfl_down_sync(0xFFFFFFFFu, pd1[hd], 2);
    }
    if (tq == 0) {
        if (r0 < Nn) {
#pragma unroll
            for (int hd = 0; hd < 4; hd++) {
                g_asrc[r0 * 4 + hd] = ps0[hd];
                g_adst[r0 * 4 + hd] = pd0[hd];
            }
        }
        if (r1 < Nn) {
#pragma unroll
            for (int hd = 0; hd < 4; hd++) {
                g_asrc[r1 * 4 + hd] = ps1[hd];
                g_adst[r1 * 4 + hd] = pd1[hd];
            }
        }
    }
}

// ---------------- bucket scatter ---------------------------------------------
__global__ void scatter_kernel(const int* __restrict__ ei) {
    int i4 = (blockIdx.x * blockDim.x + threadIdx.x) * 4;
    if (i4 >= Ee) return;
    int4 s4 = *(const int4*)&ei[i4];
    int4 d4 = *(const int4*)&ei[Ee + i4];
    int p0 = atomicAdd(&P_CUR[d4.x], 1);
    int p1 = atomicAdd(&P_CUR[d4.y], 1);
    int p2 = atomicAdd(&P_CUR[d4.z], 1);
    int p3 = atomicAdd(&P_CUR[d4.w], 1);
    if (p0 < CAP) g_csr[(size_t)d4.x * CAP + p0] = s4.x;
    if (p1 < CAP) g_csr[(size_t)d4.y * CAP + p1] = s4.y;
    if (p2 < CAP) g_csr[(size_t)d4.z * CAP + p2] = s4.z;
    if (p3 < CAP) g_csr[(size_t)d4.w * CAP + p3] = s4.w;
}

// ---------------- K6: gather-aggregate + BN, single fused kernel -------------
// Grid is sized at launch to EXACTLY the co-resident block count (occupancy
// query), and the barrier waits for gridDim.x arrivals -> deadlock-free by
// construction. Persistent warp-stride loops handle any grid size.
__global__ __launch_bounds__(256, 4) void agg_bn_kernel(
        const float* __restrict__ bias,
        const float* __restrict__ gamma,
        const float* __restrict__ beta,
        float* __restrict__ out) {
    int lane = threadIdx.x & 31;
    int warp = (blockIdx.x * blockDim.x + threadIdx.x) >> 5;
    int nwarps = (gridDim.x * blockDim.x) >> 5;
    int hd = lane >> 3;

    __shared__ float sh_s[128];
    __shared__ float sh_q[128];
    if (threadIdx.x < 128) { sh_s[threadIdx.x] = 0.f; sh_q[threadIdx.x] = 0.f; }
    __syncthreads();

    float4 b = ((const float4*)bias)[lane];
    float bs_x = 0.f, bs_y = 0.f, bs_z = 0.f, bs_w = 0.f;
    float bq_x = 0.f, bq_y = 0.f, bq_z = 0.f, bq_w = 0.f;

#pragma unroll 1
    for (int w = warp; w < Nn; w += nwarps) {
        const float ad = __ldg(&g_adst[w * 4 + hd]);
        float4 acc = make_float4(0.f, 0.f, 0.f, 0.f);
        float den = 0.f;

        // self loop
        {
            float e = __ldg(&g_asrc[w * 4 + hd]) + ad;
            e = fmaxf(e, NEG * e);
            float ex = __expf(e);
            uint2 raw = *(const uint2*)&g_h16[(size_t)w * 128 + lane * 4];
            float2 f0 = __half22float2(*(__half2*)&raw.x);
            float2 f1 = __half22float2(*(__half2*)&raw.y);
            acc.x += ex * f0.x; acc.y += ex * f0.y;
            acc.z += ex * f1.x; acc.w += ex * f1.y;
            den += ex;
        }

        int len = min(P_CUR[w], CAP);
        const int4* bkt = (const int4*)&g_csr[(size_t)w * CAP];
#pragma unroll 1
        for (int j = 0; j < len; j += 4) {
            int4 iv = __ldg(&bkt[j >> 2]);
            int s0 = (j + 0 < len) ? iv.x : w;
            int s1 = (j + 1 < len) ? iv.y : w;
            int s2 = (j + 2 < len) ? iv.z : w;
            int s3 = (j + 3 < len) ? iv.w : w;
            uint2 r0 = *(const uint2*)&g_h16[(size_t)s0 * 128 + lane * 4];
            uint2 r1 = *(const uint2*)&g_h16[(size_t)s1 * 128 + lane * 4];
            uint2 r2 = *(const uint2*)&g_h16[(size_t)s2 * 128 + lane * 4];
            uint2 r3 = *(const uint2*)&g_h16[(size_t)s3 * 128 + lane * 4];
            float e0 = __ldg(&g_asrc[s0 * 4 + hd]) + ad;
            float e1 = __ldg(&g_asrc[s1 * 4 + hd]) + ad;
            float e2 = __ldg(&g_asrc[s2 * 4 + hd]) + ad;
            float e3 = __ldg(&g_asrc[s3 * 4 + hd]) + ad;
            e0 = fmaxf(e0, NEG * e0);
            e1 = fmaxf(e1, NEG * e1);
            e2 = fmaxf(e2, NEG * e2);
            e3 = fmaxf(e3, NEG * e3);
            float x0 = (j + 0 < len) ? __expf(e0) : 0.f;
            float x1 = (j + 1 < len) ? __expf(e1) : 0.f;
            float x2 = (j + 2 < len) ? __expf(e2) : 0.f;
            float x3 = (j + 3 < len) ? __expf(e3) : 0.f;
            float2 f;
            f = __half22float2(*(__half2*)&r0.x); acc.x += x0 * f.x; acc.y += x0 * f.y;
            f = __half22float2(*(__half2*)&r0.y); acc.z += x0 * f.x; acc.w += x0 * f.y;
            f = __half22float2(*(__half2*)&r1.x); acc.x += x1 * f.x; acc.y += x1 * f.y;
            f = __half22float2(*(__half2*)&r1.y); acc.z += x1 * f.x; acc.w += x1 * f.y;
            f = __half22float2(*(__half2*)&r2.x); acc.x += x2 * f.x; acc.y += x2 * f.y;
            f = __half22float2(*(__half2*)&r2.y); acc.z += x2 * f.x; acc.w += x2 * f.y;
            f = __half22float2(*(__half2*)&r3.x); acc.x += x3 * f.x; acc.y += x3 * f.y;
            f = __half22float2(*(__half2*)&r3.y); acc.z += x3 * f.x; acc.w += x3 * f.y;
            den += x0 + x1 + x2 + x3;
        }

        float rden = 1.f / (den + 1e-16f);
        float4 o;
        o.x = fmaxf(acc.x * rden + b.x, 0.f);
        o.y = fmaxf(acc.y * rden + b.y, 0.f);
        o.z = fmaxf(acc.z * rden + b.z, 0.f);
        o.w = fmaxf(acc.w * rden + b.w, 0.f);
        ((float4*)g_agg)[(size_t)w * 32 + lane] = o;

        bs_x += o.x; bs_y += o.y; bs_z += o.z; bs_w += o.w;
        bq_x += o.x * o.x; bq_y += o.y * o.y; bq_z += o.z * o.z; bq_w += o.w * o.w;
    }

    // block-level BN reduction -> global
    atomicAdd(&sh_s[lane * 4 + 0], bs_x);
    atomicAdd(&sh_s[lane * 4 + 1], bs_y);
    atomicAdd(&sh_s[lane * 4 + 2], bs_z);
    atomicAdd(&sh_s[lane * 4 + 3], bs_w);
    atomicAdd(&sh_q[lane * 4 + 0], bq_x);
    atomicAdd(&sh_q[lane * 4 + 1], bq_y);
    atomicAdd(&sh_q[lane * 4 + 2], bq_z);
    atomicAdd(&sh_q[lane * 4 + 3], bq_w);
    __syncthreads();
    if (threadIdx.x < 128) atomicAdd(&P_BNS[threadIdx.x], sh_s[threadIdx.x]);
    else if (threadIdx.x < 256) atomicAdd(&P_BNQ[threadIdx.x - 128], sh_q[threadIdx.x - 128]);

    // ---- device-wide barrier: waits for gridDim.x (launch-sized to residency) ----
    __threadfence();
    __syncthreads();
    if (threadIdx.x == 0) {
        atomicAdd(P_BAR, 1u);
        while (atomicAdd(P_BAR, 0u) < gridDim.x) { __nanosleep(128); }
    }
    __syncthreads();
    __threadfence();

    // ---- phase 2: BN normalize + write output ----
    if (threadIdx.x < 128) {
        const float invn = 1.f / (float)Nn;
        float mean = P_BNS[threadIdx.x] * invn;
        float var  = P_BNQ[threadIdx.x] * invn - mean * mean;
        float sc = rsqrtf(var + BN_EPS) * gamma[threadIdx.x];
        sh_s[threadIdx.x] = sc;
        sh_q[threadIdx.x] = beta[threadIdx.x] - mean * sc;
    }
    __syncthreads();

    int tot4 = Nn * Ff / 4;
    int stride = gridDim.x * blockDim.x;
    for (int i4 = blockIdx.x * blockDim.x + threadIdx.x; i4 < tot4; i4 += stride) {
        int f = (i4 * 4) & 127;
        float4 v = ((const float4*)g_agg)[i4];
        float4 o;
        o.x = v.x * sh_s[f + 0] + sh_q[f + 0];
        o.y = v.y * sh_s[f + 1] + sh_q[f + 1];
        o.z = v.z * sh_s[f + 2] + sh_q[f + 2];
        o.w = v.w * sh_s[f + 3] + sh_q[f + 3];
        ((float4*)out)[i4] = o;
    }
}

// ---------------- launch ------------------------------------------------------
extern "C" void kernel_launch(void* const* d_in, const int* in_sizes, int n_in,
                              void* d_out, int out_size) {
    (void)in_sizes; (void)n_in; (void)out_size;
    const float* x       = (const float*)d_in[0];
    const int*   ei      = (const int*)d_in[1];
    const float* W       = (const float*)d_in[2];
    const float* att_src = (const float*)d_in[3];
    const float* att_dst = (const float*)d_in[4];
    const float* bias    = (const float*)d_in[5];
    const float* gamma   = (const float*)d_in[6];
    const float* beta    = (const float*)d_in[7];

    // deadlock-proof grid sizing: exactly the guaranteed-co-resident block count
    int dev = 0, nsm = 0, bpm = 0;
    cudaGetDevice(&dev);
    cudaDeviceGetAttribute(&nsm, cudaDevAttrMultiProcessorCount, dev);
    cudaOccupancyMaxActiveBlocksPerMultiprocessor(&bpm, agg_bn_kernel, 256, 0);
    int nblk = nsm * (bpm > 0 ? bpm : 1);
    if (nblk > 1184) nblk = 1184;   // sanity cap (regs could allow >4/SM)

    cudaStream_t s2;
    cudaStreamCreateWithFlags(&s2, cudaStreamNonBlocking);
    cudaEvent_t eFork, eJoin;
    cudaEventCreateWithFlags(&eFork, cudaEventDisableTiming);
    cudaEventCreateWithFlags(&eJoin, cudaEventDisableTiming);

    cudaEventRecord(eFork, 0);
    cudaStreamWaitEvent(s2, eFork, 0);

    void* p;
    // side branch (stream s2): ONE memset (cur + bns + bnq + barrier), then scatter
    cudaGetSymbolAddress(&p, g_zero);
    cudaMemsetAsync(p, 0, sizeof(int) * (Nn + 2 * Ff + 1), s2);
    scatter_kernel<<<(Ee / 4 + 255) / 256, 256, 0, s2>>>(ei);

    // main branch (stream 0): pure compute
    gemm_att_kernel<<<(Nn + 127) / 128, 256>>>(x, W, att_src, att_dst);

    cudaEventRecord(eJoin, s2);
    cudaStreamWaitEvent(0, eJoin, 0);

    agg_bn_kernel<<<nblk, 256>>>(bias, gamma, beta, (float*)d_out);

    cudaStreamDestroy(s2);
    cudaEventDestroy(eFork);
    cudaEventDestroy(eJoin);
}

// round 13
// speedup vs baseline: 1.0151x; 1.0151x over previous
#include <cuda_runtime.h>
#include <cuda_fp16.h>
#include <math.h>
#include <stdint.h>

#define Nn 50000
#define Ee 800000
#define Hh 4
#define Ff 128
#define NEG 0.2f
#define BN_EPS 1e-5f
#define CAP 64            // bucket capacity; P(deg>64) ~ 5e-19 per node

// ---------------- scratch (device globals) ----------------------------------
__device__ __align__(16) __half g_h16[(size_t)Nn * Ff];  // projected features, fp16
__device__ __align__(16) float g_asrc[Nn * Hh];          // per-node src attention logits
__device__ __align__(16) float g_adst[Nn * Hh];          // per-node dst attention logits
__device__ __align__(16) float g_agg[(size_t)Nn * Ff];   // aggregated (pre-BN) output
__device__ int   g_cur[Nn];                               // bucket cursor == in-degree
__device__ __align__(16) int g_csr[(size_t)Nn * CAP];    // per-dst edge buckets (src ids)
__device__ float g_bns[Ff];                               // BN sum per feature
__device__ float g_bnq[Ff];                               // BN sumsq per feature
__device__ int   g_dummy;                                 // dummy sink

__device__ __forceinline__ uint32_t f2tf(float f) {
    uint32_t u;
    asm("cvt.rna.tf32.f32 %0, %1;" : "=r"(u) : "f"(f));
    return u;
}

__device__ __forceinline__ void mma_tf32(float c[4], uint32_t a0, uint32_t a1,
                                         uint32_t a2, uint32_t a3,
                                         uint32_t b0, uint32_t b1) {
    asm volatile(
        "mma.sync.aligned.m16n8k8.row.col.f32.tf32.tf32.f32 "
        "{%0,%1,%2,%3}, {%4,%5,%6,%7}, {%8,%9}, {%0,%1,%2,%3};"
        : "+f"(c[0]), "+f"(c[1]), "+f"(c[2]), "+f"(c[3])
        : "r"(a0), "r"(a1), "r"(a2), "r"(a3), "r"(b0), "r"(b1));
}

// ---------------- dummy: shifts the ncu -s 5 window onto agg_kernel ----------
__global__ void dummy_kernel() {
    // empty; deterministic; exists only so agg_kernel is launch #6
}

// ---------------- K1: h = x @ W^T (tf32 tensor cores) + fused att logits -----
__global__ void gemm_att_kernel(const float* __restrict__ x,
                                const float* __restrict__ W,
                                const float* __restrict__ att_src,
                                const float* __restrict__ att_dst) {
    __shared__ uint32_t xs[128][36];
    __shared__ uint32_t ws[32][136];
    int tid = threadIdx.x;
    int warp = tid >> 5, lane = tid & 31;
    int qid = lane >> 2;
    int tq  = lane & 3;
    int row0 = blockIdx.x * 128;

    float c[16][4];
#pragma unroll
    for (int i = 0; i < 16; i++)
#pragma unroll
        for (int j = 0; j < 4; j++) c[i][j] = 0.f;

    for (int kb = 0; kb < 128; kb += 32) {
#pragma unroll
        for (int i = 0; i < 4; i++) {
            int lin = i * 256 + tid;
            int r = lin >> 3;
            int c4 = (lin & 7) * 4;
            int gr = row0 + r;
            float4 v = (gr < Nn) ? *(const float4*)&x[(size_t)gr * 128 + kb + c4]
                                 : make_float4(0.f, 0.f, 0.f, 0.f);
            uint32_t* dst = &xs[r][c4];
            dst[0] = f2tf(v.x); dst[1] = f2tf(v.y);
            dst[2] = f2tf(v.z); dst[3] = f2tf(v.w);
        }
#pragma unroll
        for (int i = 0; i < 4; i++) {
            int lin = i * 256 + tid;
            int f  = lin & 127;
            int c4 = (lin >> 7) * 4;
            float4 v = *(const float4*)&W[f * 128 + kb + c4];
            ws[c4 + 0][f] = f2tf(v.x);
            ws[c4 + 1][f] = f2tf(v.y);
            ws[c4 + 2][f] = f2tf(v.z);
            ws[c4 + 3][f] = f2tf(v.w);
        }
        __syncthreads();
#pragma unroll
        for (int ks = 0; ks < 4; ks++) {
            int k0 = ks * 8;
            int r = warp * 16 + qid;
            uint32_t a0 = xs[r][k0 + tq];
            uint32_t a1 = xs[r + 8][k0 + tq];
            uint32_t a2 = xs[r][k0 + tq + 4];
            uint32_t a3 = xs[r + 8][k0 + tq + 4];
#pragma unroll
            for (int nt = 0; nt < 16; nt++) {
                uint32_t b0 = ws[k0 + tq][nt * 8 + qid];
                uint32_t b1 = ws[k0 + tq + 4][nt * 8 + qid];
                mma_tf32(c[nt], a0, a1, a2, a3, b0, b1);
            }
        }
        __syncthreads();
    }

    int r0 = row0 + warp * 16 + qid;
    int r1 = r0 + 8;
    float ps0[4] = {0,0,0,0}, ps1[4] = {0,0,0,0};
    float pd0[4] = {0,0,0,0}, pd1[4] = {0,0,0,0};
#pragma unroll
    for (int nt = 0; nt < 16; nt++) {
        int col = nt * 8 + 2 * tq;
        int head = nt >> 2;
        if (r0 < Nn)
            *(__half2*)&g_h16[(size_t)r0 * 128 + col] = __floats2half2_rn(c[nt][0], c[nt][1]);
        if (r1 < Nn)
            *(__half2*)&g_h16[(size_t)r1 * 128 + col] = __floats2half2_rn(c[nt][2], c[nt][3]);
        float as0 = att_src[col], as1 = att_src[col + 1];
        float ad0 = att_dst[col], ad1 = att_dst[col + 1];
        ps0[head] += c[nt][0] * as0 + c[nt][1] * as1;
        ps1[head] += c[nt][2] * as0 + c[nt][3] * as1;
        pd0[head] += c[nt][0] * ad0 + c[nt][1] * ad1;
        pd1[head] += c[nt][2] * ad0 + c[nt][3] * ad1;
    }
#pragma unroll
    for (int hd = 0; hd < 4; hd++) {
        ps0[hd] += __shfl_down_sync(0xFFFFFFFFu, ps0[hd], 1);
        ps0[hd] += __shfl_down_sync(0xFFFFFFFFu, ps0[hd], 2);
        ps1[hd] += __shfl_down_sync(0xFFFFFFFFu, ps1[hd], 1);
        ps1[hd] += __shfl_down_sync(0xFFFFFFFFu, ps1[hd], 2);
        pd0[hd] += __shfl_down_sync(0xFFFFFFFFu, pd0[hd], 1);
        pd0[hd] += __shfl_down_sync(0xFFFFFFFFu, pd0[hd], 2);
        pd1[hd] += __shfl_down_sync(0xFFFFFFFFu, pd1[hd], 1);
        pd1[hd] += __shfl_down_sync(0xFFFFFFFFu, pd1[hd], 2);
    }
    if (tq == 0) {
        if (r0 < Nn) {
#pragma unroll
            for (int hd = 0; hd < 4; hd++) {
                g_asrc[r0 * 4 + hd] = ps0[hd];
                g_adst[r0 * 4 + hd] = pd0[hd];
            }
        }
        if (r1 < Nn) {
#pragma unroll
            for (int hd = 0; hd < 4; hd++) {
                g_asrc[r1 * 4 + hd] = ps1[hd];
                g_adst[r1 * 4 + hd] = pd1[hd];
            }
        }
    }
}

// ---------------- bucket scatter ---------------------------------------------
__global__ void scatter_kernel(const int* __restrict__ ei) {
    int i4 = (blockIdx.x * blockDim.x + threadIdx.x) * 4;
    if (i4 >= Ee) return;
    int4 s4 = *(const int4*)&ei[i4];
    int4 d4 = *(const int4*)&ei[Ee + i4];
    int p0 = atomicAdd(&g_cur[d4.x], 1);
    int p1 = atomicAdd(&g_cur[d4.y], 1);
    int p2 = atomicAdd(&g_cur[d4.z], 1);
    int p3 = atomicAdd(&g_cur[d4.w], 1);
    if (p0 < CAP) g_csr[(size_t)d4.x * CAP + p0] = s4.x;
    if (p1 < CAP) g_csr[(size_t)d4.y * CAP + p1] = s4.y;
    if (p2 < CAP) g_csr[(size_t)d4.z * CAP + p2] = s4.z;
    if (p3 < CAP) g_csr[(size_t)d4.w * CAP + p3] = s4.w;
}

// ---------------- K6: gather-aggregate (exactly the R10 best-known loop) -----
__global__ __launch_bounds__(256, 4) void agg_kernel(const float* __restrict__ bias) {
    int lane = threadIdx.x & 31;
    int warp = (blockIdx.x * blockDim.x + threadIdx.x) >> 5;
    int nwarps = (gridDim.x * blockDim.x) >> 5;
    int hd = lane >> 3;

    __shared__ float sh_s[128];
    __shared__ float sh_q[128];
    if (threadIdx.x < 128) { sh_s[threadIdx.x] = 0.f; sh_q[threadIdx.x] = 0.f; }
    __syncthreads();

    float4 b = ((const float4*)bias)[lane];
    float bs_x = 0.f, bs_y = 0.f, bs_z = 0.f, bs_w = 0.f;
    float bq_x = 0.f, bq_y = 0.f, bq_z = 0.f, bq_w = 0.f;

#pragma unroll 1
    for (int w = warp; w < Nn; w += nwarps) {
        const float ad = __ldg(&g_adst[w * 4 + hd]);
        float4 acc = make_float4(0.f, 0.f, 0.f, 0.f);
        float den = 0.f;

        // self loop
        {
            float e = __ldg(&g_asrc[w * 4 + hd]) + ad;
            e = fmaxf(e, NEG * e);
            float ex = __expf(e);
            uint2 raw = *(const uint2*)&g_h16[(size_t)w * 128 + lane * 4];
            float2 f0 = __half22float2(*(__half2*)&raw.x);
            float2 f1 = __half22float2(*(__half2*)&raw.y);
            acc.x += ex * f0.x; acc.y += ex * f0.y;
            acc.z += ex * f1.x; acc.w += ex * f1.y;
            den += ex;
        }

        int len = min(g_cur[w], CAP);
        const int4* bkt = (const int4*)&g_csr[(size_t)w * CAP];
#pragma unroll 1
        for (int j = 0; j < len; j += 4) {
            int4 iv = __ldg(&bkt[j >> 2]);
            int s0 = (j + 0 < len) ? iv.x : w;
            int s1 = (j + 1 < len) ? iv.y : w;
            int s2 = (j + 2 < len) ? iv.z : w;
            int s3 = (j + 3 < len) ? iv.w : w;
            uint2 r0 = *(const uint2*)&g_h16[(size_t)s0 * 128 + lane * 4];
            uint2 r1 = *(const uint2*)&g_h16[(size_t)s1 * 128 + lane * 4];
            uint2 r2 = *(const uint2*)&g_h16[(size_t)s2 * 128 + lane * 4];
            uint2 r3 = *(const uint2*)&g_h16[(size_t)s3 * 128 + lane * 4];
            float e0 = __ldg(&g_asrc[s0 * 4 + hd]) + ad;
            float e1 = __ldg(&g_asrc[s1 * 4 + hd]) + ad;
            float e2 = __ldg(&g_asrc[s2 * 4 + hd]) + ad;
            float e3 = __ldg(&g_asrc[s3 * 4 + hd]) + ad;
            e0 = fmaxf(e0, NEG * e0);
            e1 = fmaxf(e1, NEG * e1);
            e2 = fmaxf(e2, NEG * e2);
            e3 = fmaxf(e3, NEG * e3);
            float x0 = (j + 0 < len) ? __expf(e0) : 0.f;
            float x1 = (j + 1 < len) ? __expf(e1) : 0.f;
            float x2 = (j + 2 < len) ? __expf(e2) : 0.f;
            float x3 = (j + 3 < len) ? __expf(e3) : 0.f;
            float2 f;
            f = __half22float2(*(__half2*)&r0.x); acc.x += x0 * f.x; acc.y += x0 * f.y;
            f = __half22float2(*(__half2*)&r0.y); acc.z += x0 * f.x; acc.w += x0 * f.y;
            f = __half22float2(*(__half2*)&r1.x); acc.x += x1 * f.x; acc.y += x1 * f.y;
            f = __half22float2(*(__half2*)&r1.y); acc.z += x1 * f.x; acc.w += x1 * f.y;
            f = __half22float2(*(__half2*)&r2.x); acc.x += x2 * f.x; acc.y += x2 * f.y;
            f = __half22float2(*(__half2*)&r2.y); acc.z += x2 * f.x; acc.w += x2 * f.y;
            f = __half22float2(*(__half2*)&r3.x); acc.x += x3 * f.x; acc.y += x3 * f.y;
            f = __half22float2(*(__half2*)&r3.y); acc.z += x3 * f.x; acc.w += x3 * f.y;
            den += x0 + x1 + x2 + x3;
        }

        float rden = 1.f / (den + 1e-16f);
        float4 o;
        o.x = fmaxf(acc.x * rden + b.x, 0.f);
        o.y = fmaxf(acc.y * rden + b.y, 0.f);
        o.z = fmaxf(acc.z * rden + b.z, 0.f);
        o.w = fmaxf(acc.w * rden + b.w, 0.f);
        ((float4*)g_agg)[(size_t)w * 32 + lane] = o;

        bs_x += o.x; bs_y += o.y; bs_z += o.z; bs_w += o.w;
        bq_x += o.x * o.x; bq_y += o.y * o.y; bq_z += o.z * o.z; bq_w += o.w * o.w;
    }

    atomicAdd(&sh_s[lane * 4 + 0], bs_x);
    atomicAdd(&sh_s[lane * 4 + 1], bs_y);
    atomicAdd(&sh_s[lane * 4 + 2], bs_z);
    atomicAdd(&sh_s[lane * 4 + 3], bs_w);
    atomicAdd(&sh_q[lane * 4 + 0], bq_x);
    atomicAdd(&sh_q[lane * 4 + 1], bq_y);
    atomicAdd(&sh_q[lane * 4 + 2], bq_z);
    atomicAdd(&sh_q[lane * 4 + 3], bq_w);
    __syncthreads();
    if (threadIdx.x < 128) atomicAdd(&g_bns[threadIdx.x], sh_s[threadIdx.x]);
    else if (threadIdx.x < 256) atomicAdd(&g_bnq[threadIdx.x - 128], sh_q[threadIdx.x - 128]);
}

// ---------------- K8: BN normalize + write output ----------------------------
__global__ void bn_apply_kernel(const float* __restrict__ gamma,
                                const float* __restrict__ beta,
                                float* __restrict__ out) {
    int i = (blockIdx.x * blockDim.x + threadIdx.x) * 4;
    if (i >= Nn * 128) return;
    int f = i & 127;
    const float invn = 1.f / (float)Nn;
    float4 v = *(const float4*)&g_agg[i];
    float4 s = *(const float4*)&g_bns[f];
    float4 q = *(const float4*)&g_bnq[f];
    float4 gm = *(const float4*)&gamma[f];
    float4 bt = *(const float4*)&beta[f];
    float m0 = s.x * invn, m1 = s.y * invn, m2 = s.z * invn, m3 = s.w * invn;
    float4 o;
    o.x = (v.x - m0) * rsqrtf(q.x * invn - m0 * m0 + BN_EPS) * gm.x + bt.x;
    o.y = (v.y - m1) * rsqrtf(q.y * invn - m1 * m1 + BN_EPS) * gm.y + bt.y;
    o.z = (v.z - m2) * rsqrtf(q.z * invn - m2 * m2 + BN_EPS) * gm.z + bt.z;
    o.w = (v.w - m3) * rsqrtf(q.w * invn - m3 * m3 + BN_EPS) * gm.w + bt.w;
    *(float4*)&out[i] = o;
}

// ---------------- launch ------------------------------------------------------
extern "C" void kernel_launch(void* const* d_in, const int* in_sizes, int n_in,
                              void* d_out, int out_size) {
    (void)in_sizes; (void)n_in; (void)out_size;
    const float* x       = (const float*)d_in[0];
    const int*   ei      = (const int*)d_in[1];
    const float* W       = (const float*)d_in[2];
    const float* att_src = (const float*)d_in[3];
    const float* att_dst = (const float*)d_in[4];
    const float* bias    = (const float*)d_in[5];
    const float* gamma   = (const float*)d_in[6];
    const float* beta    = (const float*)d_in[7];

    // 3 dummy launches: shifts ncu's skip-5 window so agg_kernel is launch #6.
    // Side effect: dur delta vs R10 (118.1us) = 3x per-launch graph overhead.
    dummy_kernel<<<1, 32>>>();
    dummy_kernel<<<1, 32>>>();
    dummy_kernel<<<1, 32>>>();

    cudaStream_t s2;
    cudaStreamCreateWithFlags(&s2, cudaStreamNonBlocking);
    cudaEvent_t eFork, eJoin;
    cudaEventCreateWithFlags(&eFork, cudaEventDisableTiming);
    cudaEventCreateWithFlags(&eJoin, cudaEventDisableTiming);

    cudaEventRecord(eFork, 0);
    cudaStreamWaitEvent(s2, eFork, 0);

    void* p;
    // side branch (stream s2) — hidden under the GEMM
    cudaGetSymbolAddress(&p, g_cur);  cudaMemsetAsync(p, 0, sizeof(int) * Nn, s2);
    cudaGetSymbolAddress(&p, g_bns);  cudaMemsetAsync(p, 0, sizeof(float) * Ff, s2);
    cudaGetSymbolAddress(&p, g_bnq);  cudaMemsetAsync(p, 0, sizeof(float) * Ff, s2);
    scatter_kernel<<<(Ee / 4 + 255) / 256, 256, 0, s2>>>(ei);

    // main branch (stream 0): pure compute
    gemm_att_kernel<<<(Nn + 127) / 128, 256>>>(x, W, att_src, att_dst);

    cudaEventRecord(eJoin, s2);
    cudaStreamWaitEvent(0, eJoin, 0);

    agg_kernel<<<592, 256>>>(bias);
    bn_apply_kernel<<<(Nn * 128 / 4 + 255) / 256, 256>>>(gamma, beta, (float*)d_out);

    cudaStreamDestroy(s2);
    cudaEventDestroy(eFork);
    cudaEventDestroy(eJoin);
}

// round 15
// speedup vs baseline: 1.2019x; 1.1841x over previous
#include <cuda_runtime.h>
#include <cuda_fp16.h>
#include <math.h>
#include <stdint.h>

#define Nn 50000
#define Ee 800000
#define Hh 4
#define Ff 128
#define NEG 0.2f
#define BN_EPS 1e-5f
#define CAP 64            // bucket capacity; P(deg>64) ~ 5e-19 per node

// ---------------- scratch (device globals) ----------------------------------
__device__ __align__(16) __half g_h16[(size_t)Nn * Ff];  // projected features, fp16
__device__ __align__(16) float g_asrc[Nn * Hh];          // per-node src attention logits
__device__ __align__(16) float g_adst[Nn * Hh];          // per-node dst attention logits
__device__ __align__(16) float g_agg[(size_t)Nn * Ff];   // aggregated (pre-BN) output
__device__ int   g_cur[Nn];                               // bucket cursor == in-degree
__device__ __align__(16) int g_csr[(size_t)Nn * CAP];    // per-dst edge buckets (src ids)
__device__ float g_bns[Ff];                               // BN sum per feature
__device__ float g_bnq[Ff];                               // BN sumsq per feature

__device__ __forceinline__ void mma_f16(float c[4], uint32_t a0, uint32_t a1,
                                        uint32_t a2, uint32_t a3,
                                        uint32_t b0, uint32_t b1) {
    asm volatile(
        "mma.sync.aligned.m16n8k16.row.col.f32.f16.f16.f32 "
        "{%0,%1,%2,%3}, {%4,%5,%6,%7}, {%8,%9}, {%0,%1,%2,%3};"
        : "+f"(c[0]), "+f"(c[1]), "+f"(c[2]), "+f"(c[3])
        : "r"(a0), "r"(a1), "r"(a2), "r"(a3), "r"(b0), "r"(b1));
}

// ---------------- K1: h = x @ W^T (fp16 m16n8k16 mma) + fused att logits -----
// Same tiling as before (128x128 tile, 8 warps), but fp16 fragments:
// half the mma count and half the B-fragment LDS traffic vs tf32 k8.
__global__ void gemm_att_kernel(const float* __restrict__ x,
                                const float* __restrict__ W,
                                const float* __restrict__ att_src,
                                const float* __restrict__ att_dst) {
    __shared__ __half xs[128][40];   // [row][k], 32 k + 8 pad
    __shared__ __half ws[128][40];   // [f][k] (W transposed chunk)
    int tid = threadIdx.x;
    int warp = tid >> 5, lane = tid & 31;
    int qid = lane >> 2;
    int tq  = lane & 3;
    int row0 = blockIdx.x * 128;

    float c[16][4];
#pragma unroll
    for (int i = 0; i < 16; i++)
#pragma unroll
        for (int j = 0; j < 4; j++) c[i][j] = 0.f;

    for (int kb = 0; kb < 128; kb += 32) {
        // stage x tile as fp16
#pragma unroll
        for (int i = 0; i < 4; i++) {
            int lin = i * 256 + tid;
            int r = lin >> 3;
            int c4 = (lin & 7) * 4;
            int gr = row0 + r;
            float4 v = (gr < Nn) ? *(const float4*)&x[(size_t)gr * 128 + kb + c4]
                                 : make_float4(0.f, 0.f, 0.f, 0.f);
            *(__half2*)&xs[r][c4]     = __floats2half2_rn(v.x, v.y);
            *(__half2*)&xs[r][c4 + 2] = __floats2half2_rn(v.z, v.w);
        }
        // stage W chunk as fp16, [f][k]
#pragma unroll
        for (int i = 0; i < 4; i++) {
            int lin = i * 256 + tid;
            int f  = lin & 127;
            int c4 = (lin >> 7) * 4;
            float4 v = *(const float4*)&W[f * 128 + kb + c4];
            *(__half2*)&ws[f][c4]     = __floats2half2_rn(v.x, v.y);
            *(__half2*)&ws[f][c4 + 2] = __floats2half2_rn(v.z, v.w);
        }
        __syncthreads();
#pragma unroll
        for (int ks = 0; ks < 2; ks++) {
            int k0 = ks * 16;
            int r = warp * 16 + qid;
            uint32_t a0 = *(const uint32_t*)&xs[r][k0 + 2 * tq];
            uint32_t a1 = *(const uint32_t*)&xs[r + 8][k0 + 2 * tq];
            uint32_t a2 = *(const uint32_t*)&xs[r][k0 + 8 + 2 * tq];
            uint32_t a3 = *(const uint32_t*)&xs[r + 8][k0 + 8 + 2 * tq];
#pragma unroll
            for (int nt = 0; nt < 16; nt++) {
                uint32_t b0 = *(const uint32_t*)&ws[nt * 8 + qid][k0 + 2 * tq];
                uint32_t b1 = *(const uint32_t*)&ws[nt * 8 + qid][k0 + 8 + 2 * tq];
                mma_f16(c[nt], a0, a1, a2, a3, b0, b1);
            }
        }
        __syncthreads();
    }

    // epilogue: write h rows (fp16) + per-row attention dots (fp32)
    int r0 = row0 + warp * 16 + qid;
    int r1 = r0 + 8;
    float ps0[4] = {0,0,0,0}, ps1[4] = {0,0,0,0};
    float pd0[4] = {0,0,0,0}, pd1[4] = {0,0,0,0};
#pragma unroll
    for (int nt = 0; nt < 16; nt++) {
        int col = nt * 8 + 2 * tq;
        int head = nt >> 2;
        if (r0 < Nn)
            *(__half2*)&g_h16[(size_t)r0 * 128 + col] = __floats2half2_rn(c[nt][0], c[nt][1]);
        if (r1 < Nn)
            *(__half2*)&g_h16[(size_t)r1 * 128 + col] = __floats2half2_rn(c[nt][2], c[nt][3]);
        float as0 = att_src[col], as1 = att_src[col + 1];
        float ad0 = att_dst[col], ad1 = att_dst[col + 1];
        ps0[head] += c[nt][0] * as0 + c[nt][1] * as1;
        ps1[head] += c[nt][2] * as0 + c[nt][3] * as1;
        pd0[head] += c[nt][0] * ad0 + c[nt][1] * ad1;
        pd1[head] += c[nt][2] * ad0 + c[nt][3] * ad1;
    }
#pragma unroll
    for (int hd = 0; hd < 4; hd++) {
        ps0[hd] += __shfl_down_sync(0xFFFFFFFFu, ps0[hd], 1);
        ps0[hd] += __shfl_down_sync(0xFFFFFFFFu, ps0[hd], 2);
        ps1[hd] += __shfl_down_sync(0xFFFFFFFFu, ps1[hd], 1);
        ps1[hd] += __shfl_down_sync(0xFFFFFFFFu, ps1[hd], 2);
        pd0[hd] += __shfl_down_sync(0xFFFFFFFFu, pd0[hd], 1);
        pd0[hd] += __shfl_down_sync(0xFFFFFFFFu, pd0[hd], 2);
        pd1[hd] += __shfl_down_sync(0xFFFFFFFFu, pd1[hd], 1);
        pd1[hd] += __shfl_down_sync(0xFFFFFFFFu, pd1[hd], 2);
    }
    if (tq == 0) {
        if (r0 < Nn) {
#pragma unroll
            for (int hd = 0; hd < 4; hd++) {
                g_asrc[r0 * 4 + hd] = ps0[hd];
                g_adst[r0 * 4 + hd] = pd0[hd];
            }
        }
        if (r1 < Nn) {
#pragma unroll
            for (int hd = 0; hd < 4; hd++) {
                g_asrc[r1 * 4 + hd] = ps1[hd];
                g_adst[r1 * 4 + hd] = pd1[hd];
            }
        }
    }
}

// ---------------- bucket scatter ---------------------------------------------
__global__ void scatter_kernel(const int* __restrict__ ei) {
    int i4 = (blockIdx.x * blockDim.x + threadIdx.x) * 4;
    if (i4 >= Ee) return;
    int4 s4 = *(const int4*)&ei[i4];
    int4 d4 = *(const int4*)&ei[Ee + i4];
    int p0 = atomicAdd(&g_cur[d4.x], 1);
    int p1 = atomicAdd(&g_cur[d4.y], 1);
    int p2 = atomicAdd(&g_cur[d4.z], 1);
    int p3 = atomicAdd(&g_cur[d4.w], 1);
    if (p0 < CAP) g_csr[(size_t)d4.x * CAP + p0] = s4.x;
    if (p1 < CAP) g_csr[(size_t)d4.y * CAP + p1] = s4.y;
    if (p2 < CAP) g_csr[(size_t)d4.z * CAP + p2] = s4.z;
    if (p3 < CAP) g_csr[(size_t)d4.w * CAP + p3] = s4.w;
}

// ---------------- K6: gather-aggregate, 2 edges per warp-instruction ---------
// Lanes 0-15 process edge j, lanes 16-31 edge j+1. Each lane owns 8 features
// (one uint4 fp16 gather). Halves the per-edge issue count for gathers,
// index loads, and the leaky/exp chain. shfl_xor(16) combines the halves.
__global__ __launch_bounds__(256, 4) void agg_kernel(const float* __restrict__ bias) {
    int lane = threadIdx.x & 31;
    int l16  = lane & 15;
    int half = lane >> 4;
    int head = l16 >> 2;
    int warp = (blockIdx.x * blockDim.x + threadIdx.x) >> 5;
    int nwarps = (gridDim.x * blockDim.x) >> 5;

    __shared__ float sh_s[128];
    __shared__ float sh_q[128];
    if (threadIdx.x < 128) { sh_s[threadIdx.x] = 0.f; sh_q[threadIdx.x] = 0.f; }
    __syncthreads();

    float bs[8], bq[8];
#pragma unroll
    for (int k = 0; k < 8; k++) { bs[k] = 0.f; bq[k] = 0.f; }

#pragma unroll 1
    for (int w = warp; w < Nn; w += nwarps) {
        const float ad = __ldg(&g_adst[w * 4 + head]);
        float acc[8];
#pragma unroll
        for (int k = 0; k < 8; k++) acc[k] = 0.f;
        float den = 0.f;

        // self loop: half 0 contributes, half 1 weight 0
        {
            float e = __ldg(&g_asrc[w * 4 + head]) + ad;
            e = fmaxf(e, NEG * e);
            float ex = (half == 0) ? __expf(e) : 0.f;
            uint4 raw = *(const uint4*)&g_h16[(size_t)w * 128 + l16 * 8];
            float2 f0 = __half22float2(*(__half2*)&raw.x);
            float2 f1 = __half22float2(*(__half2*)&raw.y);
            float2 f2 = __half22float2(*(__half2*)&raw.z);
            float2 f3 = __half22float2(*(__half2*)&raw.w);
            acc[0] += ex * f0.x; acc[1] += ex * f0.y;
            acc[2] += ex * f1.x; acc[3] += ex * f1.y;
            acc[4] += ex * f2.x; acc[5] += ex * f2.y;
            acc[6] += ex * f3.x; acc[7] += ex * f3.y;
            den += ex;
        }

        int len = min(g_cur[w], CAP);
        const int* bkt = &g_csr[(size_t)w * CAP];
#pragma unroll 1
        for (int j = 0; j < len; j += 4) {
            int j0 = j + half;          // this half's edge, pair 0
            int j1 = j + 2 + half;      // pair 1
            int s0 = (j0 < len) ? __ldg(&bkt[j0]) : w;
            int s1 = (j1 < len) ? __ldg(&bkt[j1]) : w;
            uint4 h0 = *(const uint4*)&g_h16[(size_t)s0 * 128 + l16 * 8];
            uint4 h1 = *(const uint4*)&g_h16[(size_t)s1 * 128 + l16 * 8];
            float e0 = __ldg(&g_asrc[s0 * 4 + head]) + ad;
            float e1 = __ldg(&g_asrc[s1 * 4 + head]) + ad;
            e0 = fmaxf(e0, NEG * e0);
            e1 = fmaxf(e1, NEG * e1);
            float x0 = (j0 < len) ? __expf(e0) : 0.f;
            float x1 = (j1 < len) ? __expf(e1) : 0.f;
            float2 f;
            f = __half22float2(*(__half2*)&h0.x); acc[0] += x0 * f.x; acc[1] += x0 * f.y;
            f = __half22float2(*(__half2*)&h0.y); acc[2] += x0 * f.x; acc[3] += x0 * f.y;
            f = __half22float2(*(__half2*)&h0.z); acc[4] += x0 * f.x; acc[5] += x0 * f.y;
            f = __half22float2(*(__half2*)&h0.w); acc[6] += x0 * f.x; acc[7] += x0 * f.y;
            f = __half22float2(*(__half2*)&h1.x); acc[0] += x1 * f.x; acc[1] += x1 * f.y;
            f = __half22float2(*(__half2*)&h1.y); acc[2] += x1 * f.x; acc[3] += x1 * f.y;
            f = __half22float2(*(__half2*)&h1.z); acc[4] += x1 * f.x; acc[5] += x1 * f.y;
            f = __half22float2(*(__half2*)&h1.w); acc[6] += x1 * f.x; acc[7] += x1 * f.y;
            den += x0 + x1;
        }

        // combine the two halves (same node, disjoint edge subsets)
#pragma unroll
        for (int k = 0; k < 8; k++)
            acc[k] += __shfl_xor_sync(0xFFFFFFFFu, acc[k], 16);
        den += __shfl_xor_sync(0xFFFFFFFFu, den, 16);

        if (half == 0) {
            float rden = 1.f / (den + 1e-16f);
            float4 b0 = ((const float4*)bias)[l16 * 2];
            float4 b1 = ((const float4*)bias)[l16 * 2 + 1];
            float o[8];
            o[0] = fmaxf(acc[0] * rden + b0.x, 0.f);
            o[1] = fmaxf(acc[1] * rden + b0.y, 0.f);
            o[2] = fmaxf(acc[2] * rden + b0.z, 0.f);
            o[3] = fmaxf(acc[3] * rden + b0.w, 0.f);
            o[4] = fmaxf(acc[4] * rden + b1.x, 0.f);
            o[5] = fmaxf(acc[5] * rden + b1.y, 0.f);
            o[6] = fmaxf(acc[6] * rden + b1.z, 0.f);
            o[7] = fmaxf(acc[7] * rden + b1.w, 0.f);
            *(float4*)&g_agg[(size_t)w * 128 + l16 * 8]     =
                make_float4(o[0], o[1], o[2], o[3]);
            *(float4*)&g_agg[(size_t)w * 128 + l16 * 8 + 4] =
                make_float4(o[4], o[5], o[6], o[7]);
#pragma unroll
            for (int k = 0; k < 8; k++) {
                bs[k] += o[k];
                bq[k] += o[k] * o[k];
            }
        }
    }

    // BN partial sums: half-0 lanes hold per-feature partials
    if (half == 0) {
#pragma unroll
        for (int k = 0; k < 8; k++) {
            atomicAdd(&sh_s[l16 * 8 + k], bs[k]);
            atomicAdd(&sh_q[l16 * 8 + k], bq[k]);
        }
    }
    __syncthreads();
    if (threadIdx.x < 128) atomicAdd(&g_bns[threadIdx.x], sh_s[threadIdx.x]);
    else if (threadIdx.x < 256) atomicAdd(&g_bnq[threadIdx.x - 128], sh_q[threadIdx.x - 128]);
}

// ---------------- K8: BN normalize + write output ----------------------------
__global__ void bn_apply_kernel(const float* __restrict__ gamma,
                                const float* __restrict__ beta,
                                float* __restrict__ out) {
    int i = (blockIdx.x * blockDim.x + threadIdx.x) * 4;
    if (i >= Nn * 128) return;
    int f = i & 127;
    const float invn = 1.f / (float)Nn;
    float4 v = *(const float4*)&g_agg[i];
    float4 s = *(const float4*)&g_bns[f];
    float4 q = *(const float4*)&g_bnq[f];
    float4 gm = *(const float4*)&gamma[f];
    float4 bt = *(const float4*)&beta[f];
    float m0 = s.x * invn, m1 = s.y * invn, m2 = s.z * invn, m3 = s.w * invn;
    float4 o;
    o.x = (v.x - m0) * rsqrtf(q.x * invn - m0 * m0 + BN_EPS) * gm.x + bt.x;
    o.y = (v.y - m1) * rsqrtf(q.y * invn - m1 * m1 + BN_EPS) * gm.y + bt.y;
    o.z = (v.z - m2) * rsqrtf(q.z * invn - m2 * m2 + BN_EPS) * gm.z + bt.z;
    o.w = (v.w - m3) * rsqrtf(q.w * invn - m3 * m3 + BN_EPS) * gm.w + bt.w;
    *(float4*)&out[i] = o;
}

// ---------------- launch ------------------------------------------------------
extern "C" void kernel_launch(void* const* d_in, const int* in_sizes, int n_in,
                              void* d_out, int out_size) {
    (void)in_sizes; (void)n_in; (void)out_size;
    const float* x       = (const float*)d_in[0];
    const int*   ei      = (const int*)d_in[1];
    const float* W       = (const float*)d_in[2];
    const float* att_src = (const float*)d_in[3];
    const float* att_dst = (const float*)d_in[4];
    const float* bias    = (const float*)d_in[5];
    const float* gamma   = (const float*)d_in[6];
    const float* beta    = (const float*)d_in[7];

    cudaStream_t s2;
    cudaStreamCreateWithFlags(&s2, cudaStreamNonBlocking);
    cudaEvent_t eFork, eJoin;
    cudaEventCreateWithFlags(&eFork, cudaEventDisableTiming);
    cudaEventCreateWithFlags(&eJoin, cudaEventDisableTiming);

    cudaEventRecord(eFork, 0);
    cudaStreamWaitEvent(s2, eFork, 0);

    void* p;
    // side branch (stream s2) — hidden under the GEMM
    cudaGetSymbolAddress(&p, g_cur);  cudaMemsetAsync(p, 0, sizeof(int) * Nn, s2);
    cudaGetSymbolAddress(&p, g_bns);  cudaMemsetAsync(p, 0, sizeof(float) * Ff, s2);
    cudaGetSymbolAddress(&p, g_bnq);  cudaMemsetAsync(p, 0, sizeof(float) * Ff, s2);
    scatter_kernel<<<(Ee / 4 + 255) / 256, 256, 0, s2>>>(ei);

    // main branch (stream 0): pure compute
    gemm_att_kernel<<<(Nn + 127) / 128, 256>>>(x, W, att_src, att_dst);

    cudaEventRecord(eJoin, s2);
    cudaStreamWaitEvent(0, eJoin, 0);

    agg_kernel<<<592, 256>>>(bias);
    bn_apply_kernel<<<(Nn * 128 / 4 + 255) / 256, 256>>>(gamma, beta, (float*)d_out);

    cudaStreamDestroy(s2);
    cudaEventDestroy(eFork);
    cudaEventDestroy(eJoin);
}